// round 8
// baseline (speedup 1.0000x reference)
#include <cuda_runtime.h>
#include <cuda_bf16.h>
#include <cstdint>

#define CC 16
#define NN 10000
#define EE 40000
#define FF 256
#define CFGF 18

// ---- scratch (static __device__ arrays; no allocations anywhere) ----
__device__ float g_bufA[CC * NN * FF];   // ping (x)
__device__ float g_bufB[CC * NN * FF];   // pong (x)
__device__ float g_yl [CC * NN * FF];    // x @ wl
__device__ float g_yr [CC * NN * FF];    // x @ wr + bl
__device__ float g_base[NN * FF];
__device__ float g_T   [CFGF * 8 * FF];
__device__ float g_invdeg[NN];
__device__ float g_pool[CC * FF];
__device__ int   g_deg[NN];
__device__ int   g_cursor[NN];
__device__ int   g_rowptr[NN + 1];
__device__ int   g_colidx[EE];
__device__ __nv_bfloat16 g_whi[4 * 512 * 256];  // weights split hi, [layer][n][k]
__device__ __nv_bfloat16 g_wlo[4 * 512 * 256];  // weights split lo

// ================= helpers =================
__device__ __forceinline__ void mma16816(float* d, const uint32_t* a, const uint32_t* b) {
    asm volatile(
        "mma.sync.aligned.m16n8k16.row.col.f32.bf16.bf16.f32 "
        "{%0,%1,%2,%3}, {%4,%5,%6,%7}, {%8,%9}, {%0,%1,%2,%3};"
        : "+f"(d[0]), "+f"(d[1]), "+f"(d[2]), "+f"(d[3])
        : "r"(a[0]), "r"(a[1]), "r"(a[2]), "r"(a[3]), "r"(b[0]), "r"(b[1]));
}
// split a float2 into packed bf16x2 hi and residual-lo (element .x = low half)
__device__ __forceinline__ void split2(float2 v, uint32_t& hi, uint32_t& lo) {
    __nv_bfloat16 hx = __float2bfloat16(v.x), hy = __float2bfloat16(v.y);
    __nv_bfloat162 hp; hp.x = hx; hp.y = hy;
    __nv_bfloat162 lp = __floats2bfloat162_rn(v.x - __bfloat162float(hx),
                                              v.y - __bfloat162float(hy));
    hi = *(uint32_t*)&hp; lo = *(uint32_t*)&lp;
}

// ================= prologue kernels =================
// blocks [0,144): T table;  blocks [144, 144+NN): base
__global__ void k_tablebase(const float* __restrict__ emb_layout,
                            const float* __restrict__ lin_w,
                            const float* __restrict__ lin_b,
                            const float* __restrict__ x_feat,
                            const int*   __restrict__ x_op,
                            const float* __restrict__ emb_op) {
    int j = threadIdx.x;
    if (blockIdx.x < 144) {
        int blk = blockIdx.x;
        int k = blk >> 3, v = blk & 7;
        float acc = 0.f;
#pragma unroll
        for (int d = 0; d < 4; d++)
            acc += emb_layout[v * 4 + d] * lin_w[(140 + k * 4 + d) * FF + j];
        g_T[blk * FF + j] = acc;
        return;
    }
    int n = blockIdx.x - 144;
    __shared__ float sf[144];
    if (j < 140) sf[j] = x_feat[n * 140 + j];
    if (j >= 140 && j < 144) {
        int op = x_op[n];
        sf[j] = emb_op[op * 4 + (j - 140)];
    }
    __syncthreads();
    float acc = lin_b[j];
#pragma unroll 4
    for (int d = 0; d < 140; d++) acc += sf[d] * lin_w[d * FF + j];
#pragma unroll
    for (int d = 0; d < 4; d++)   acc += sf[140 + d] * lin_w[(212 + d) * FF + j];
    g_base[n * FF + j] = acc;
}

__global__ void k_small_zero() {
    int i = blockIdx.x * blockDim.x + threadIdx.x;
    if (i < NN) { g_deg[i] = 0; g_cursor[i] = 0; }
    if (i < CC * FF) g_pool[i] = 0.f;
}
__global__ void k_deg_acc(const int* __restrict__ edge_index) {
    int e = blockIdx.x * blockDim.x + threadIdx.x;
    if (e < EE) atomicAdd(&g_deg[edge_index[EE + e]], 1);
}
__global__ void k_scan() {
    __shared__ int csum[256];
    int t = threadIdx.x;
    const int CH = (NN + 255) / 256;  // 40
    int base = t * CH;
    int s = 0;
    for (int i = 0; i < CH; i++) {
        int idx = base + i;
        if (idx < NN) s += g_deg[idx];
    }
    csum[t] = s;
    __syncthreads();
    if (t == 0) {
        int acc = 0;
        for (int i = 0; i < 256; i++) { int v = csum[i]; csum[i] = acc; acc += v; }
        g_rowptr[NN] = acc;
    }
    __syncthreads();
    int acc = csum[t];
    for (int i = 0; i < CH; i++) {
        int idx = base + i;
        if (idx < NN) {
            g_rowptr[idx] = acc;
            int d = g_deg[idx];
            acc += d;
            g_invdeg[idx] = 1.0f / fmaxf((float)d, 1.0f);
        }
    }
}
__global__ void k_fill(const int* __restrict__ edge_index) {
    int e = blockIdx.x * blockDim.x + threadIdx.x;
    if (e < EE) {
        int dst = edge_index[EE + e];
        int p = atomicAdd(&g_cursor[dst], 1);
        g_colidx[g_rowptr[dst] + p] = edge_index[e];
    }
}

__global__ void k_initx(const int* __restrict__ x_node_cfg) {
    int n = blockIdx.x, c = blockIdx.y, j = threadIdx.x;
    __shared__ int scfg[CFGF];
    if (j < CFGF) scfg[j] = x_node_cfg[((size_t)c * NN + n) * CFGF + j];
    __syncthreads();
    float acc = g_base[n * FF + j];
#pragma unroll
    for (int k = 0; k < CFGF; k++)
        acc += g_T[(k * 8 + scfg[k]) * FF + j];
    g_bufA[((size_t)c * NN + n) * FF + j] = acc;
}

// split all 4 layers' weights into bf16 hi/lo in [layer][n(512)][k(256)] layout
__global__ void k_wsplit(const float* __restrict__ conv_wl,
                         const float* __restrict__ conv_wr) {
    int t = blockIdx.x * 256 + threadIdx.x;   // 0 .. 4*512*256-1
    int l = t >> 17;
    int rem = t & 131071;
    int n = rem >> 8, k = rem & 255;
    const float* w = (n < 256) ? (conv_wl + (size_t)l * 65536)
                               : (conv_wr + (size_t)l * 65536);
    float v = w[k * 256 + (n & 255)];
    __nv_bfloat16 h = __float2bfloat16(v);
    g_whi[t] = h;
    g_wlo[t] = __float2bfloat16(v - __bfloat162float(h));
}

// ================= HMMA bf16x3 GEMM — no shared memory =================
// y = x @ [wl | wr]  (M=160000, K=256, N=512)
// CTA 128x128; grid (4 col tiles, 1250 row tiles); 8 warps: 2(m) x 4(n)
// Both operands loaded directly from global in fragment layout:
//   A: LDG.64 pairs, fp32 -> bf16 hi/lo split in registers
//   B: aligned uint32 loads from prebuilt bf16 hi/lo tables (L1/L2 resident)
__global__ __launch_bounds__(256, 2) void k_gemm_mma(int srcA, int layer,
                                                     const float* __restrict__ bl) {
    const float* __restrict__ x = srcA ? g_bufA : g_bufB;

    const int tid = threadIdx.x;
    const int wid = tid >> 5, lane = tid & 31;
    const int col0 = blockIdx.x * 128;
    const int m0 = blockIdx.y * 128;
    const int wm = (wid & 1) * 64;       // warp m base
    const int wn = (wid >> 1) * 32;      // warp n base

    float acc[4][4][4];
#pragma unroll
    for (int i = 0; i < 4; i++)
#pragma unroll
        for (int j = 0; j < 4; j++)
#pragma unroll
            for (int q = 0; q < 4; q++) acc[i][j][q] = 0.f;

    // A fragment base: row = m0+wm+ma*16+(lane>>2) (+8), k = kt*16+(lane&3)*2 (+1,+8,+9)
    const float* apb = x + (size_t)(m0 + wm + (lane >> 2)) * FF + (lane & 3) * 2;
    // B fragment base: n = col0+wn+na*8+(lane>>2), k = kt*16+(lane&3)*2
    const size_t boff = ((size_t)(layer * 512 + col0 + wn + (lane >> 2))) * 256
                        + (lane & 3) * 2;
    const __nv_bfloat16* bhb = g_whi + boff;
    const __nv_bfloat16* blb = g_wlo + boff;

    for (int kc = 0; kc < 4; kc++) {
#pragma unroll
        for (int ks = 0; ks < 4; ks++) {
            const int kk = kc * 64 + ks * 16;
            // ---- B fragments (4 n-atoms, hi & lo) ----
            uint32_t bhf[4][2], blf[4][2];
#pragma unroll
            for (int na = 0; na < 4; na++) {
                const __nv_bfloat16* ph = bhb + na * 8 * 256 + kk;
                const __nv_bfloat16* pl = blb + na * 8 * 256 + kk;
                bhf[na][0] = *(const uint32_t*)(ph);
                bhf[na][1] = *(const uint32_t*)(ph + 8);
                blf[na][0] = *(const uint32_t*)(pl);
                blf[na][1] = *(const uint32_t*)(pl + 8);
            }
            // ---- A fragments per m-atom, convert, MMA ----
#pragma unroll
            for (int ma = 0; ma < 4; ma++) {
                const float* pa = apb + (size_t)(ma * 16) * FF + kk;
                float2 v00 = *(const float2*)(pa);            // (r,   k..k+1)
                float2 v10 = *(const float2*)(pa + 8 * FF);   // (r+8, k..k+1)
                float2 v01 = *(const float2*)(pa + 8);        // (r,   k+8..k+9)
                float2 v11 = *(const float2*)(pa + 8 * FF + 8);
                uint32_t ah[4], al[4];
                split2(v00, ah[0], al[0]);
                split2(v10, ah[1], al[1]);
                split2(v01, ah[2], al[2]);
                split2(v11, ah[3], al[3]);
#pragma unroll
                for (int na = 0; na < 4; na++) {
                    mma16816(acc[ma][na], ah, bhf[na]);
                    mma16816(acc[ma][na], ah, blf[na]);
                    mma16816(acc[ma][na], al, bhf[na]);
                }
            }
        }
    }

    // ---- epilogue ----
    const int quad = lane >> 2, qt = lane & 3;
    const bool isR = (col0 >= 256);
    float* __restrict__ out = isR ? g_yr : g_yl;
#pragma unroll
    for (int ma = 0; ma < 4; ma++) {
#pragma unroll
        for (int na = 0; na < 4; na++) {
            int cl = (col0 + wn + na * 8 + qt * 2) & 255;
            float b0 = 0.f, b1 = 0.f;
            if (isR) { b0 = bl[cl]; b1 = bl[cl + 1]; }
            int row = m0 + wm + ma * 16 + quad;
            float2 v0; v0.x = acc[ma][na][0] + b0; v0.y = acc[ma][na][1] + b1;
            float2 v1; v1.x = acc[ma][na][2] + b0; v1.y = acc[ma][na][3] + b1;
            *(float2*)(out + (size_t)row * FF + cl)       = v0;
            *(float2*)(out + (size_t)(row + 8) * FF + cl) = v1;
        }
    }
}

// ================= SAGE combine (CSR gather) =================
__global__ __launch_bounds__(256) void k_sage(int dstA) {
    float* __restrict__ out = dstA ? g_bufA : g_bufB;
    int n = blockIdx.x;
    int j = threadIdx.x;
    int e0 = g_rowptr[n], e1 = g_rowptr[n + 1];
    float inv = g_invdeg[n];

    // preload yr (16 independent loads overlap the gather chain)
    float yrv[CC];
#pragma unroll
    for (int c = 0; c < CC; c++)
        yrv[c] = g_yr[((size_t)c * NN + n) * FF + j];

    float sacc[CC];
#pragma unroll
    for (int c = 0; c < CC; c++) sacc[c] = 0.f;

    __shared__ int sc[64];
    for (int eb = e0; eb < e1; eb += 64) {
        int m = min(64, e1 - eb);
        __syncthreads();
        if (j < m) sc[j] = g_colidx[eb + j];
        __syncthreads();
        for (int q = 0; q < m; q++) {
            int src = sc[q];
            const float* p = g_yl + (size_t)src * FF + j;
#pragma unroll
            for (int c = 0; c < CC; c++)
                sacc[c] += p[(size_t)c * NN * FF];
        }
    }
#pragma unroll
    for (int c = 0; c < CC; c++) {
        size_t o = ((size_t)c * NN + n) * FF + j;
        out[o] = fmaxf(sacc[c] * inv + yrv[c], 0.f);
    }
}

__global__ void k_pool() {
    int c = blockIdx.x, chunk = blockIdx.y, j = threadIdx.x;
    int n0 = chunk * 250;
    float acc = 0.f;
    for (int n = n0; n < n0 + 250; n++)
        acc += g_bufA[((size_t)c * NN + n) * FF + j];
    atomicAdd(&g_pool[c * FF + j], acc);
}

__global__ __launch_bounds__(256) void k_mlp(
    const float* __restrict__ w1, const float* __restrict__ b1,
    const float* __restrict__ w2, const float* __restrict__ b2,
    const float* __restrict__ w3, const float* __restrict__ b3,
    float* __restrict__ outp)
{
    __shared__ float g[CC][FF];
    __shared__ float h[CC][FF];
    int j = threadIdx.x;
    const float scale = 1.0f / (float)NN;
#pragma unroll
    for (int c = 0; c < CC; c++) g[c][j] = g_pool[c * FF + j] * scale;
    __syncthreads();
    {
        float accs[CC];
#pragma unroll
        for (int c = 0; c < CC; c++) accs[c] = 0.f;
        for (int k = 0; k < FF; k++) {
            float wv = w1[k * FF + j];
#pragma unroll
            for (int c = 0; c < CC; c++) accs[c] += g[c][k] * wv;
        }
        float bb = b1[j];
#pragma unroll
        for (int c = 0; c < CC; c++) h[c][j] = fmaxf(accs[c] + bb, 0.f);
    }
    __syncthreads();
    {
        float accs[CC];
#pragma unroll
        for (int c = 0; c < CC; c++) accs[c] = 0.f;
        for (int k = 0; k < FF; k++) {
            float wv = w2[k * FF + j];
#pragma unroll
            for (int c = 0; c < CC; c++) accs[c] += h[c][k] * wv;
        }
        float bb = b2[j];
#pragma unroll
        for (int c = 0; c < CC; c++) g[c][j] = fmaxf(accs[c] + bb, 0.f);
    }
    __syncthreads();
    {
        float wv = w3[j];
#pragma unroll
        for (int c = 0; c < CC; c++) h[c][j] = g[c][j] * wv;
        __syncthreads();
        if (j < CC) {
            float s = 0.f;
            for (int k = 0; k < FF; k++) s += h[j][k];
            outp[j] = s + b3[0];
        }
    }
}

// ---------------------------------------------------------------------
extern "C" void kernel_launch(void* const* d_in, const int* in_sizes, int n_in,
                              void* d_out, int out_size) {
    const int*   x_node_cfg = (const int*)  d_in[0];
    const float* x_feat     = (const float*)d_in[1];
    const int*   x_op       = (const int*)  d_in[2];
    const int*   edge_index = (const int*)  d_in[3];
    const float* emb_op     = (const float*)d_in[4];
    const float* emb_layout = (const float*)d_in[5];
    const float* lin_w      = (const float*)d_in[6];
    const float* lin_b      = (const float*)d_in[7];
    const float* conv_wl    = (const float*)d_in[8];
    const float* conv_bl    = (const float*)d_in[9];
    const float* conv_wr    = (const float*)d_in[10];
    const float* w1         = (const float*)d_in[11];
    const float* b1         = (const float*)d_in[12];
    const float* w2         = (const float*)d_in[13];
    const float* b2         = (const float*)d_in[14];
    const float* w3         = (const float*)d_in[15];
    const float* b3         = (const float*)d_in[16];
    float* outp = (float*)d_out;

    // launch order: gemm layer 0 lands at profiled slot (index 3)
    k_wsplit<<<(4 * 512 * 256) / 256, 256>>>(conv_wl, conv_wr);            // 0
    k_tablebase<<<144 + NN, FF>>>(emb_layout, lin_w, lin_b,
                                  x_feat, x_op, emb_op);                    // 1
    k_initx<<<dim3(NN, CC), FF>>>(x_node_cfg);                              // 2
    k_gemm_mma<<<dim3(4, (CC * NN) / 128), 256>>>(1, 0, conv_bl);           // 3 (profiled)

    // CSR build (only needed by k_sage)
    k_small_zero<<<(NN + 255) / 256, 256>>>();                              // 4
    k_deg_acc<<<(EE + 255) / 256, 256>>>(edge_index);                       // 5
    k_scan<<<1, 256>>>();                                                   // 6
    k_fill<<<(EE + 255) / 256, 256>>>(edge_index);                          // 7
    k_sage<<<NN, FF>>>(0);                                                  // 8: layer0 -> bufB

    for (int i = 1; i < 4; i++) {
        int srcA = (i % 2 == 0) ? 1 : 0;
        k_gemm_mma<<<dim3(4, (CC * NN) / 128), 256>>>(
            srcA, i, conv_bl + (size_t)i * FF);
        k_sage<<<NN, FF>>>(srcA ? 0 : 1);
    }

    k_pool<<<dim3(CC, NN / 250), FF>>>();
    k_mlp<<<1, FF>>>(w1, b1, w2, b2, w3, b3, outp);
}

// round 9
// speedup vs baseline: 1.1081x; 1.1081x over previous
#include <cuda_runtime.h>
#include <cuda_bf16.h>
#include <cstdint>

#define CC 16
#define NN 10000
#define EE 40000
#define FF 256
#define CFGF 18

// ---- scratch (static __device__ arrays; no allocations anywhere) ----
// x kept as SPLIT bf16 (hi + residual lo), ping/pong
__device__ __nv_bfloat16 g_xhA[CC * NN * FF];
__device__ __nv_bfloat16 g_xlA[CC * NN * FF];
__device__ __nv_bfloat16 g_xhB[CC * NN * FF];
__device__ __nv_bfloat16 g_xlB[CC * NN * FF];
__device__ __nv_bfloat16 g_ylb[CC * NN * FF];   // x@wl, bf16, [node][c][j] (82MB, L2-resident)
__device__ float g_yr [CC * NN * FF];           // x@wr + bl, fp32, [c*NN+n][j]
__device__ float g_base[NN * FF];
__device__ float g_T   [CFGF * 8 * FF];
__device__ float g_invdeg[NN];
__device__ float g_pool[CC * FF];
__device__ int   g_deg[NN];
__device__ int   g_cursor[NN];
__device__ int   g_rowptr[NN + 1];
__device__ int   g_colidx[EE];
__device__ __nv_bfloat16 g_whi[4 * 512 * 256];  // weights split hi, [layer][n][k]
__device__ __nv_bfloat16 g_wlo[4 * 512 * 256];  // weights split lo

// ================= helpers =================
#define SWZ(o) ((o) ^ (((o) >> 3) & 0x70))

__device__ __forceinline__ uint32_t s2u(const void* p) {
    uint32_t a;
    asm("{ .reg .u64 t; cvta.to.shared.u64 t, %1; cvt.u32.u64 %0, t; }"
        : "=r"(a) : "l"(p));
    return a;
}
__device__ __forceinline__ void ldm_x4(uint32_t* r, uint32_t addr) {
    asm volatile("ldmatrix.sync.aligned.m8n8.x4.shared.b16 {%0,%1,%2,%3}, [%4];"
                 : "=r"(r[0]), "=r"(r[1]), "=r"(r[2]), "=r"(r[3]) : "r"(addr));
}
__device__ __forceinline__ void ldm_x2(uint32_t* r, uint32_t addr) {
    asm volatile("ldmatrix.sync.aligned.m8n8.x2.shared.b16 {%0,%1}, [%2];"
                 : "=r"(r[0]), "=r"(r[1]) : "r"(addr));
}
__device__ __forceinline__ void mma16816(float* d, const uint32_t* a, const uint32_t* b) {
    asm volatile(
        "mma.sync.aligned.m16n8k16.row.col.f32.bf16.bf16.f32 "
        "{%0,%1,%2,%3}, {%4,%5,%6,%7}, {%8,%9}, {%0,%1,%2,%3};"
        : "+f"(d[0]), "+f"(d[1]), "+f"(d[2]), "+f"(d[3])
        : "r"(a[0]), "r"(a[1]), "r"(a[2]), "r"(a[3]), "r"(b[0]), "r"(b[1]));
}
__device__ __forceinline__ void cp16(uint32_t saddr, const void* gptr) {
    asm volatile("cp.async.ca.shared.global [%0], [%1], 16;"
                 :: "r"(saddr), "l"(gptr) : "memory");
}
// split float2 -> packed bf16x2 hi and residual lo
__device__ __forceinline__ void split2(float2 v, uint32_t& hi, uint32_t& lo) {
    __nv_bfloat16 hx = __float2bfloat16(v.x), hy = __float2bfloat16(v.y);
    __nv_bfloat162 hp; hp.x = hx; hp.y = hy;
    __nv_bfloat162 lp = __floats2bfloat162_rn(v.x - __bfloat162float(hx),
                                              v.y - __bfloat162float(hy));
    hi = *(uint32_t*)&hp; lo = *(uint32_t*)&lp;
}

// ================= prologue kernels =================
__global__ void k_tablebase(const float* __restrict__ emb_layout,
                            const float* __restrict__ lin_w,
                            const float* __restrict__ lin_b,
                            const float* __restrict__ x_feat,
                            const int*   __restrict__ x_op,
                            const float* __restrict__ emb_op) {
    int j = threadIdx.x;
    if (blockIdx.x < 144) {
        int blk = blockIdx.x;
        int k = blk >> 3, v = blk & 7;
        float acc = 0.f;
#pragma unroll
        for (int d = 0; d < 4; d++)
            acc += emb_layout[v * 4 + d] * lin_w[(140 + k * 4 + d) * FF + j];
        g_T[blk * FF + j] = acc;
        return;
    }
    int n = blockIdx.x - 144;
    __shared__ float sf[144];
    if (j < 140) sf[j] = x_feat[n * 140 + j];
    if (j >= 140 && j < 144) {
        int op = x_op[n];
        sf[j] = emb_op[op * 4 + (j - 140)];
    }
    __syncthreads();
    float acc = lin_b[j];
#pragma unroll 4
    for (int d = 0; d < 140; d++) acc += sf[d] * lin_w[d * FF + j];
#pragma unroll
    for (int d = 0; d < 4; d++)   acc += sf[140 + d] * lin_w[(212 + d) * FF + j];
    g_base[n * FF + j] = acc;
}

__global__ void k_small_zero() {
    int i = blockIdx.x * blockDim.x + threadIdx.x;
    if (i < NN) { g_deg[i] = 0; g_cursor[i] = 0; }
    if (i < CC * FF) g_pool[i] = 0.f;
}
__global__ void k_deg_acc(const int* __restrict__ edge_index) {
    int e = blockIdx.x * blockDim.x + threadIdx.x;
    if (e < EE) atomicAdd(&g_deg[edge_index[EE + e]], 1);
}
__global__ void k_scan() {
    __shared__ int csum[256];
    int t = threadIdx.x;
    const int CH = (NN + 255) / 256;  // 40
    int base = t * CH;
    int s = 0;
    for (int i = 0; i < CH; i++) {
        int idx = base + i;
        if (idx < NN) s += g_deg[idx];
    }
    csum[t] = s;
    __syncthreads();
    if (t == 0) {
        int acc = 0;
        for (int i = 0; i < 256; i++) { int v = csum[i]; csum[i] = acc; acc += v; }
        g_rowptr[NN] = acc;
    }
    __syncthreads();
    int acc = csum[t];
    for (int i = 0; i < CH; i++) {
        int idx = base + i;
        if (idx < NN) {
            g_rowptr[idx] = acc;
            int d = g_deg[idx];
            acc += d;
            g_invdeg[idx] = 1.0f / fmaxf((float)d, 1.0f);
        }
    }
}
__global__ void k_fill(const int* __restrict__ edge_index) {
    int e = blockIdx.x * blockDim.x + threadIdx.x;
    if (e < EE) {
        int dst = edge_index[EE + e];
        int p = atomicAdd(&g_cursor[dst], 1);
        g_colidx[g_rowptr[dst] + p] = edge_index[e];
    }
}

// x0 = base + sum_k T[k][cfg] -> split bf16 into xhA/xlA
__global__ void k_initx(const int* __restrict__ x_node_cfg) {
    int n = blockIdx.x, c = blockIdx.y, j = threadIdx.x;
    __shared__ int scfg[CFGF];
    if (j < CFGF) scfg[j] = x_node_cfg[((size_t)c * NN + n) * CFGF + j];
    __syncthreads();
    float acc = g_base[n * FF + j];
#pragma unroll
    for (int k = 0; k < CFGF; k++)
        acc += g_T[(k * 8 + scfg[k]) * FF + j];
    size_t o = ((size_t)c * NN + n) * FF + j;
    __nv_bfloat16 h = __float2bfloat16(acc);
    g_xhA[o] = h;
    g_xlA[o] = __float2bfloat16(acc - __bfloat162float(h));
}

// split all 4 layers' weights into bf16 hi/lo in [layer][n(512)][k(256)] layout
__global__ void k_wsplit(const float* __restrict__ conv_wl,
                         const float* __restrict__ conv_wr) {
    int t = blockIdx.x * 256 + threadIdx.x;
    int l = t >> 17;
    int rem = t & 131071;
    int n = rem >> 8, k = rem & 255;
    const float* w = (n < 256) ? (conv_wl + (size_t)l * 65536)
                               : (conv_wr + (size_t)l * 65536);
    float v = w[k * 256 + (n & 255)];
    __nv_bfloat16 h = __float2bfloat16(v);
    g_whi[t] = h;
    g_wlo[t] = __float2bfloat16(v - __bfloat162float(h));
}

// ================= HMMA bf16x3 GEMM =================
// y = x @ [wl | wr]  (M=160000, K=256, N=512)
// CTA 128x128, 128 threads, 4 warps (2m x 2n), warp tile 64x64.
// smem 64KB single stage: Ahi|Alo|Bhi|Blo 16KB each; all via cp.async (pure bf16).
// 3 CTAs/SM provide load/compute overlap.
__global__ __launch_bounds__(128) void k_gemm_mma(int srcA, int layer,
                                                  const float* __restrict__ bl) {
    extern __shared__ __align__(128) char smem[];
    const __nv_bfloat16* __restrict__ xh = srcA ? g_xhA : g_xhB;
    const __nv_bfloat16* __restrict__ xl = srcA ? g_xlA : g_xlB;

    const int tid = threadIdx.x;
    const int wid = tid >> 5, lane = tid & 31;
    const int col0 = blockIdx.x * 128;
    const int m0 = blockIdx.y * 128;
    const int wm = (wid & 1) * 64;
    const int wn = (wid >> 1) * 64;

    const uint32_t sbase = s2u(smem);
    const uint32_t sA_hi = sbase;
    const uint32_t sA_lo = sbase + 16384;
    const uint32_t sB_hi = sbase + 32768;
    const uint32_t sB_lo = sbase + 49152;

    float acc[4][8][4];
#pragma unroll
    for (int i = 0; i < 4; i++)
#pragma unroll
        for (int j = 0; j < 8; j++)
#pragma unroll
            for (int q = 0; q < 4; q++) acc[i][j][q] = 0.f;

    const __nv_bfloat16* ahp = xh + (size_t)(m0 + tid) * FF;
    const __nv_bfloat16* alp = xl + (size_t)(m0 + tid) * FF;
    const __nv_bfloat16* bhp = g_whi + (size_t)(layer * 512 + col0 + tid) * 256;
    const __nv_bfloat16* blp = g_wlo + (size_t)(layer * 512 + col0 + tid) * 256;

    for (int kc = 0; kc < 4; kc++) {
        __syncthreads();   // prev compute done reading smem
#pragma unroll
        for (int q = 0; q < 8; q++) {
            uint32_t so = SWZ((uint32_t)(tid * 128 + q * 16));
            cp16(sA_hi + so, ahp + kc * 64 + q * 8);
            cp16(sA_lo + so, alp + kc * 64 + q * 8);
            cp16(sB_hi + so, bhp + kc * 64 + q * 8);
            cp16(sB_lo + so, blp + kc * 64 + q * 8);
        }
        asm volatile("cp.async.commit_group;" ::: "memory");
        asm volatile("cp.async.wait_group 0;" ::: "memory");
        __syncthreads();

#pragma unroll
        for (int ks = 0; ks < 4; ks++) {
            uint32_t bh_[8][2], bl_[8][2];
#pragma unroll
            for (int na = 0; na < 8; na++) {
                uint32_t o = (uint32_t)((wn + na * 8 + (lane & 7)) * 128);
                uint32_t seg = (uint32_t)((ks * 2 + ((lane >> 3) & 1)) * 16);
                uint32_t ad = o + (seg ^ ((o >> 3) & 0x70));
                ldm_x2(bh_[na], sB_hi + ad);
                ldm_x2(bl_[na], sB_lo + ad);
            }
#pragma unroll
            for (int ma = 0; ma < 4; ma++) {
                uint32_t o = (uint32_t)((wm + ma * 16 + (lane & 15)) * 128);
                uint32_t seg = (uint32_t)((ks * 2 + (lane >> 4)) * 16);
                uint32_t ad = o + (seg ^ ((o >> 3) & 0x70));
                uint32_t ah[4], al[4];
                ldm_x4(ah, sA_hi + ad);
                ldm_x4(al, sA_lo + ad);
#pragma unroll
                for (int na = 0; na < 8; na++) {
                    mma16816(acc[ma][na], ah, bh_[na]);
                    mma16816(acc[ma][na], ah, bl_[na]);
                    mma16816(acc[ma][na], al, bh_[na]);
                }
            }
        }
    }

    // ---- epilogue ----
    const int quad = lane >> 2, qt = lane & 3;
    const bool isR = (col0 >= 256);
#pragma unroll
    for (int ma = 0; ma < 4; ma++) {
        int row0 = m0 + wm + ma * 16 + quad;
        int row1 = row0 + 8;
        if (!isR) {
            int c0 = row0 / NN, n0 = row0 - c0 * NN;
            int c1 = row1 / NN, n1 = row1 - c1 * NN;
            uint32_t* yb = (uint32_t*)g_ylb;
#pragma unroll
            for (int na = 0; na < 8; na++) {
                int cl = col0 + wn + na * 8 + qt * 2;   // 0..255
                __nv_bfloat162 p0 = __floats2bfloat162_rn(acc[ma][na][0], acc[ma][na][1]);
                __nv_bfloat162 p1 = __floats2bfloat162_rn(acc[ma][na][2], acc[ma][na][3]);
                yb[(((size_t)n0 * CC + c0) * FF + cl) >> 1] = *(uint32_t*)&p0;
                yb[(((size_t)n1 * CC + c1) * FF + cl) >> 1] = *(uint32_t*)&p1;
            }
        } else {
#pragma unroll
            for (int na = 0; na < 8; na++) {
                int jj = (col0 - 256) + wn + na * 8 + qt * 2;  // 0..255
                float b0 = bl[jj], b1 = bl[jj + 1];
                float2 v0; v0.x = acc[ma][na][0] + b0; v0.y = acc[ma][na][1] + b1;
                float2 v1; v1.x = acc[ma][na][2] + b0; v1.y = acc[ma][na][3] + b1;
                *(float2*)(g_yr + (size_t)row0 * FF + jj) = v0;
                *(float2*)(g_yr + (size_t)row1 * FF + jj) = v1;
            }
        }
    }
}

// ================= SAGE combine (CSR gather, bf16 yl in [n][c][j]) =================
// out x = relu(mean_agg(yl) + yr), written split bf16 to xh/xl
__global__ __launch_bounds__(256) void k_sage(int dstA) {
    __nv_bfloat16* __restrict__ oxh = dstA ? g_xhA : g_xhB;
    __nv_bfloat16* __restrict__ oxl = dstA ? g_xlA : g_xlB;
    int n = blockIdx.x;
    int t = threadIdx.x;
    int jp = t & 127;        // column pair j = 2*jp
    int ch = t >> 7;         // c half: c in [ch*8, ch*8+8)
    int e0 = g_rowptr[n], e1 = g_rowptr[n + 1];
    float inv = g_invdeg[n];

    float sacc[16];
#pragma unroll
    for (int q = 0; q < 16; q++) sacc[q] = 0.f;

    __shared__ int sc[256];
    for (int eb = e0; eb < e1; eb += 256) {
        int m = min(256, e1 - eb);
        __syncthreads();
        if (t < m) sc[t] = g_colidx[eb + t];
        __syncthreads();
        for (int q = 0; q < m; q++) {
            int src = sc[q];
            const uint32_t* p = (const uint32_t*)g_ylb
                                + (size_t)src * 2048 + ch * 1024 + jp;
#pragma unroll
            for (int cc = 0; cc < 8; cc++) {
                uint32_t u = p[cc * 128];
                __nv_bfloat162 b = *(__nv_bfloat162*)&u;
                float2 f = __bfloat1622float2(b);
                sacc[cc * 2]     += f.x;
                sacc[cc * 2 + 1] += f.y;
            }
        }
    }
#pragma unroll
    for (int cc = 0; cc < 8; cc++) {
        int c = ch * 8 + cc;
        size_t o = ((size_t)c * NN + n) * FF + jp * 2;
        float2 yr2 = *(const float2*)(g_yr + o);
        float2 v;
        v.x = fmaxf(sacc[cc * 2]     * inv + yr2.x, 0.f);
        v.y = fmaxf(sacc[cc * 2 + 1] * inv + yr2.y, 0.f);
        uint32_t hi, lo;
        split2(v, hi, lo);
        ((uint32_t*)oxh)[o >> 1] = hi;
        ((uint32_t*)oxl)[o >> 1] = lo;
    }
}

__global__ void k_pool() {
    int c = blockIdx.x, chunk = blockIdx.y, j = threadIdx.x;
    int n0 = chunk * 250;
    float acc = 0.f;
    for (int n = n0; n < n0 + 250; n++) {
        size_t o = ((size_t)c * NN + n) * FF + j;
        acc += __bfloat162float(g_xhA[o]) + __bfloat162float(g_xlA[o]);
    }
    atomicAdd(&g_pool[c * FF + j], acc);
}

__global__ __launch_bounds__(256) void k_mlp(
    const float* __restrict__ w1, const float* __restrict__ b1,
    const float* __restrict__ w2, const float* __restrict__ b2,
    const float* __restrict__ w3, const float* __restrict__ b3,
    float* __restrict__ outp)
{
    __shared__ float g[CC][FF];
    __shared__ float h[CC][FF];
    int j = threadIdx.x;
    const float scale = 1.0f / (float)NN;
#pragma unroll
    for (int c = 0; c < CC; c++) g[c][j] = g_pool[c * FF + j] * scale;
    __syncthreads();
    {
        float accs[CC];
#pragma unroll
        for (int c = 0; c < CC; c++) accs[c] = 0.f;
        for (int k = 0; k < FF; k++) {
            float wv = w1[k * FF + j];
#pragma unroll
            for (int c = 0; c < CC; c++) accs[c] += g[c][k] * wv;
        }
        float bb = b1[j];
#pragma unroll
        for (int c = 0; c < CC; c++) h[c][j] = fmaxf(accs[c] + bb, 0.f);
    }
    __syncthreads();
    {
        float accs[CC];
#pragma unroll
        for (int c = 0; c < CC; c++) accs[c] = 0.f;
        for (int k = 0; k < FF; k++) {
            float wv = w2[k * FF + j];
#pragma unroll
            for (int c = 0; c < CC; c++) accs[c] += h[c][k] * wv;
        }
        float bb = b2[j];
#pragma unroll
        for (int c = 0; c < CC; c++) g[c][j] = fmaxf(accs[c] + bb, 0.f);
    }
    __syncthreads();
    {
        float wv = w3[j];
#pragma unroll
        for (int c = 0; c < CC; c++) h[c][j] = g[c][j] * wv;
        __syncthreads();
        if (j < CC) {
            float s = 0.f;
            for (int k = 0; k < FF; k++) s += h[j][k];
            outp[j] = s + b3[0];
        }
    }
}

// ---------------------------------------------------------------------
extern "C" void kernel_launch(void* const* d_in, const int* in_sizes, int n_in,
                              void* d_out, int out_size) {
    const int*   x_node_cfg = (const int*)  d_in[0];
    const float* x_feat     = (const float*)d_in[1];
    const int*   x_op       = (const int*)  d_in[2];
    const int*   edge_index = (const int*)  d_in[3];
    const float* emb_op     = (const float*)d_in[4];
    const float* emb_layout = (const float*)d_in[5];
    const float* lin_w      = (const float*)d_in[6];
    const float* lin_b      = (const float*)d_in[7];
    const float* conv_wl    = (const float*)d_in[8];
    const float* conv_bl    = (const float*)d_in[9];
    const float* conv_wr    = (const float*)d_in[10];
    const float* w1         = (const float*)d_in[11];
    const float* b1         = (const float*)d_in[12];
    const float* w2         = (const float*)d_in[13];
    const float* b2         = (const float*)d_in[14];
    const float* w3         = (const float*)d_in[15];
    const float* b3         = (const float*)d_in[16];
    float* outp = (float*)d_out;

    cudaFuncSetAttribute(k_gemm_mma, cudaFuncAttributeMaxDynamicSharedMemorySize, 65536);

    // launch order: gemm layer 0 lands at profiled slot (index 3)
    k_wsplit<<<(4 * 512 * 256) / 256, 256>>>(conv_wl, conv_wr);            // 0
    k_tablebase<<<144 + NN, FF>>>(emb_layout, lin_w, lin_b,
                                  x_feat, x_op, emb_op);                    // 1
    k_initx<<<dim3(NN, CC), FF>>>(x_node_cfg);                              // 2
    k_gemm_mma<<<dim3(4, (CC * NN) / 128), 128, 65536>>>(1, 0, conv_bl);    // 3 (profiled)

    // CSR build (only needed by k_sage)
    k_small_zero<<<(NN + 255) / 256, 256>>>();                              // 4
    k_deg_acc<<<(EE + 255) / 256, 256>>>(edge_index);                       // 5
    k_scan<<<1, 256>>>();                                                   // 6
    k_fill<<<(EE + 255) / 256, 256>>>(edge_index);                          // 7
    k_sage<<<NN, 256>>>(0);                                                 // 8: layer0 -> B

    for (int i = 1; i < 4; i++) {
        int srcA = (i % 2 == 0) ? 1 : 0;
        k_gemm_mma<<<dim3(4, (CC * NN) / 128), 128, 65536>>>(
            srcA, i, conv_bl + (size_t)i * FF);
        k_sage<<<NN, 256>>>(srcA ? 0 : 1);
    }

    k_pool<<<dim3(CC, NN / 250), FF>>>();
    k_mlp<<<1, FF>>>(w1, b1, w2, b2, w3, b3, outp);
}

// round 10
// speedup vs baseline: 1.2345x; 1.1141x over previous
#include <cuda_runtime.h>
#include <cuda_bf16.h>
#include <cstdint>

#define CC 16
#define NN 10000
#define EE 40000
#define FF 256
#define CFGF 18

// ---- scratch (static __device__ arrays; no allocations anywhere) ----
// x kept as SPLIT bf16 (hi + residual lo), ping/pong
__device__ __nv_bfloat16 g_xhA[CC * NN * FF];
__device__ __nv_bfloat16 g_xlA[CC * NN * FF];
__device__ __nv_bfloat16 g_xhB[CC * NN * FF];
__device__ __nv_bfloat16 g_xlB[CC * NN * FF];
__device__ __nv_bfloat16 g_ylb[CC * NN * FF];   // x@wl, bf16, [node][c][j] (82MB, L2-resident)
__device__ float g_yr [CC * NN * FF];           // x@wr + bl, fp32, [c*NN+n][j]
__device__ float g_base[NN * FF];
__device__ float g_T   [CFGF * 8 * FF];
__device__ float g_invdeg[NN];
__device__ float g_pool[CC * FF];
__device__ int   g_deg[NN];
__device__ int   g_cursor[NN];
__device__ int   g_rowptr[NN + 1];
__device__ int   g_colidx[EE];
__device__ __nv_bfloat16 g_whi[4 * 512 * 256];  // weights split hi, [layer][n][k]
__device__ __nv_bfloat16 g_wlo[4 * 512 * 256];  // weights split lo

// ================= helpers =================
#define SWZ(o) ((o) ^ (((o) >> 3) & 0x70))

__device__ __forceinline__ uint32_t s2u(const void* p) {
    uint32_t a;
    asm("{ .reg .u64 t; cvta.to.shared.u64 t, %1; cvt.u32.u64 %0, t; }"
        : "=r"(a) : "l"(p));
    return a;
}
__device__ __forceinline__ void ldm_x4(uint32_t* r, uint32_t addr) {
    asm volatile("ldmatrix.sync.aligned.m8n8.x4.shared.b16 {%0,%1,%2,%3}, [%4];"
                 : "=r"(r[0]), "=r"(r[1]), "=r"(r[2]), "=r"(r[3]) : "r"(addr));
}
__device__ __forceinline__ void ldm_x2(uint32_t* r, uint32_t addr) {
    asm volatile("ldmatrix.sync.aligned.m8n8.x2.shared.b16 {%0,%1}, [%2];"
                 : "=r"(r[0]), "=r"(r[1]) : "r"(addr));
}
__device__ __forceinline__ void mma16816(float* d, const uint32_t* a, const uint32_t* b) {
    asm volatile(
        "mma.sync.aligned.m16n8k16.row.col.f32.bf16.bf16.f32 "
        "{%0,%1,%2,%3}, {%4,%5,%6,%7}, {%8,%9}, {%0,%1,%2,%3};"
        : "+f"(d[0]), "+f"(d[1]), "+f"(d[2]), "+f"(d[3])
        : "r"(a[0]), "r"(a[1]), "r"(a[2]), "r"(a[3]), "r"(b[0]), "r"(b[1]));
}
__device__ __forceinline__ void cp16(uint32_t saddr, const void* gptr) {
    asm volatile("cp.async.ca.shared.global [%0], [%1], 16;"
                 :: "r"(saddr), "l"(gptr) : "memory");
}
// split float2 -> packed bf16x2 hi and residual lo
__device__ __forceinline__ void split2(float2 v, uint32_t& hi, uint32_t& lo) {
    __nv_bfloat16 hx = __float2bfloat16(v.x), hy = __float2bfloat16(v.y);
    __nv_bfloat162 hp; hp.x = hx; hp.y = hy;
    __nv_bfloat162 lp = __floats2bfloat162_rn(v.x - __bfloat162float(hx),
                                              v.y - __bfloat162float(hy));
    hi = *(uint32_t*)&hp; lo = *(uint32_t*)&lp;
}

// ================= prologue kernels =================
__global__ void k_tablebase(const float* __restrict__ emb_layout,
                            const float* __restrict__ lin_w,
                            const float* __restrict__ lin_b,
                            const float* __restrict__ x_feat,
                            const int*   __restrict__ x_op,
                            const float* __restrict__ emb_op) {
    int j = threadIdx.x;
    if (blockIdx.x < 144) {
        int blk = blockIdx.x;
        int k = blk >> 3, v = blk & 7;
        float acc = 0.f;
#pragma unroll
        for (int d = 0; d < 4; d++)
            acc += emb_layout[v * 4 + d] * lin_w[(140 + k * 4 + d) * FF + j];
        g_T[blk * FF + j] = acc;
        return;
    }
    int n = blockIdx.x - 144;
    __shared__ float sf[144];
    if (j < 140) sf[j] = x_feat[n * 140 + j];
    if (j >= 140 && j < 144) {
        int op = x_op[n];
        sf[j] = emb_op[op * 4 + (j - 140)];
    }
    __syncthreads();
    float acc = lin_b[j];
#pragma unroll 4
    for (int d = 0; d < 140; d++) acc += sf[d] * lin_w[d * FF + j];
#pragma unroll
    for (int d = 0; d < 4; d++)   acc += sf[140 + d] * lin_w[(212 + d) * FF + j];
    g_base[n * FF + j] = acc;
}

__global__ void k_small_zero() {
    int i = blockIdx.x * blockDim.x + threadIdx.x;
    if (i < NN) { g_deg[i] = 0; g_cursor[i] = 0; }
    if (i < CC * FF) g_pool[i] = 0.f;
}
__global__ void k_deg_acc(const int* __restrict__ edge_index) {
    int e = blockIdx.x * blockDim.x + threadIdx.x;
    if (e < EE) atomicAdd(&g_deg[edge_index[EE + e]], 1);
}
__global__ void k_scan() {
    __shared__ int csum[256];
    int t = threadIdx.x;
    const int CH = (NN + 255) / 256;  // 40
    int base = t * CH;
    int s = 0;
    for (int i = 0; i < CH; i++) {
        int idx = base + i;
        if (idx < NN) s += g_deg[idx];
    }
    csum[t] = s;
    __syncthreads();
    if (t == 0) {
        int acc = 0;
        for (int i = 0; i < 256; i++) { int v = csum[i]; csum[i] = acc; acc += v; }
        g_rowptr[NN] = acc;
    }
    __syncthreads();
    int acc = csum[t];
    for (int i = 0; i < CH; i++) {
        int idx = base + i;
        if (idx < NN) {
            g_rowptr[idx] = acc;
            int d = g_deg[idx];
            acc += d;
            g_invdeg[idx] = 1.0f / fmaxf((float)d, 1.0f);
        }
    }
}
__global__ void k_fill(const int* __restrict__ edge_index) {
    int e = blockIdx.x * blockDim.x + threadIdx.x;
    if (e < EE) {
        int dst = edge_index[EE + e];
        int p = atomicAdd(&g_cursor[dst], 1);
        g_colidx[g_rowptr[dst] + p] = edge_index[e];
    }
}

// x0 = base + sum_k T[k][cfg] -> split bf16 into xhA/xlA
__global__ void k_initx(const int* __restrict__ x_node_cfg) {
    int n = blockIdx.x, c = blockIdx.y, j = threadIdx.x;
    __shared__ int scfg[CFGF];
    if (j < CFGF) scfg[j] = x_node_cfg[((size_t)c * NN + n) * CFGF + j];
    __syncthreads();
    float acc = g_base[n * FF + j];
#pragma unroll
    for (int k = 0; k < CFGF; k++)
        acc += g_T[(k * 8 + scfg[k]) * FF + j];
    size_t o = ((size_t)c * NN + n) * FF + j;
    __nv_bfloat16 h = __float2bfloat16(acc);
    g_xhA[o] = h;
    g_xlA[o] = __float2bfloat16(acc - __bfloat162float(h));
}

// split all 4 layers' weights into bf16 hi/lo in [layer][n(512)][k(256)] layout
__global__ void k_wsplit(const float* __restrict__ conv_wl,
                         const float* __restrict__ conv_wr) {
    int t = blockIdx.x * 256 + threadIdx.x;
    int l = t >> 17;
    int rem = t & 131071;
    int n = rem >> 8, k = rem & 255;
    const float* w = (n < 256) ? (conv_wl + (size_t)l * 65536)
                               : (conv_wr + (size_t)l * 65536);
    float v = w[k * 256 + (n & 255)];
    __nv_bfloat16 h = __float2bfloat16(v);
    g_whi[t] = h;
    g_wlo[t] = __float2bfloat16(v - __bfloat162float(h));
}

// ================= HMMA bf16x3 GEMM =================
// y = x @ [wl | wr]  (M=160000, K=256, N=512)
// CTA 128x128, 256 threads, 8 warps (2m x 4n), warp tile 64x32 (R7 shape).
// x pre-split bf16 -> all 4 tiles via cp.async; no conversion, low regs.
// smem 64KB single stage: Ahi|Alo|Bhi|Blo 16KB each; 2 CTAs/SM overlap.
__global__ __launch_bounds__(256) void k_gemm_mma(int srcA, int layer,
                                                  const float* __restrict__ bl) {
    extern __shared__ __align__(128) char smem[];
    const __nv_bfloat16* __restrict__ xh = srcA ? g_xhA : g_xhB;
    const __nv_bfloat16* __restrict__ xl = srcA ? g_xlA : g_xlB;

    const int tid = threadIdx.x;
    const int wid = tid >> 5, lane = tid & 31;
    const int col0 = blockIdx.x * 128;
    const int m0 = blockIdx.y * 128;
    const int wm = (wid & 1) * 64;       // warp m base
    const int wn = (wid >> 1) * 32;      // warp n base

    const uint32_t sbase = s2u(smem);
    const uint32_t sA_hi = sbase;
    const uint32_t sA_lo = sbase + 16384;
    const uint32_t sB_hi = sbase + 32768;
    const uint32_t sB_lo = sbase + 49152;

    float acc[4][4][4];
#pragma unroll
    for (int i = 0; i < 4; i++)
#pragma unroll
        for (int j = 0; j < 4; j++)
#pragma unroll
            for (int q = 0; q < 4; q++) acc[i][j][q] = 0.f;

    const int r = tid >> 1, half = tid & 1;   // r: 0..127, half: 0/1 (32-elem halves)
    const __nv_bfloat16* ahp = xh + (size_t)(m0 + r) * FF + half * 32;
    const __nv_bfloat16* alp = xl + (size_t)(m0 + r) * FF + half * 32;
    const __nv_bfloat16* bhp = g_whi + (size_t)(layer * 512 + col0 + r) * 256 + half * 32;
    const __nv_bfloat16* blp = g_wlo + (size_t)(layer * 512 + col0 + r) * 256 + half * 32;

    for (int kc = 0; kc < 4; kc++) {
        __syncthreads();   // prev compute done reading smem
#pragma unroll
        for (int q = 0; q < 4; q++) {
            uint32_t so = SWZ((uint32_t)(r * 128 + half * 64 + q * 16));
            cp16(sA_hi + so, ahp + kc * 64 + q * 8);
            cp16(sA_lo + so, alp + kc * 64 + q * 8);
            cp16(sB_hi + so, bhp + kc * 64 + q * 8);
            cp16(sB_lo + so, blp + kc * 64 + q * 8);
        }
        asm volatile("cp.async.commit_group;" ::: "memory");
        asm volatile("cp.async.wait_group 0;" ::: "memory");
        __syncthreads();

#pragma unroll
        for (int ks = 0; ks < 4; ks++) {
            uint32_t bh_[4][2], bl_[4][2];
#pragma unroll
            for (int na = 0; na < 4; na++) {
                uint32_t o = (uint32_t)((wn + na * 8 + (lane & 7)) * 128);
                uint32_t seg = (uint32_t)((ks * 2 + ((lane >> 3) & 1)) * 16);
                uint32_t ad = o + (seg ^ ((o >> 3) & 0x70));
                ldm_x2(bh_[na], sB_hi + ad);
                ldm_x2(bl_[na], sB_lo + ad);
            }
#pragma unroll
            for (int ma = 0; ma < 4; ma++) {
                uint32_t o = (uint32_t)((wm + ma * 16 + (lane & 15)) * 128);
                uint32_t seg = (uint32_t)((ks * 2 + (lane >> 4)) * 16);
                uint32_t ad = o + (seg ^ ((o >> 3) & 0x70));
                uint32_t ah[4], al[4];
                ldm_x4(ah, sA_hi + ad);
                ldm_x4(al, sA_lo + ad);
#pragma unroll
                for (int na = 0; na < 4; na++) {
                    mma16816(acc[ma][na], ah, bh_[na]);
                    mma16816(acc[ma][na], ah, bl_[na]);
                    mma16816(acc[ma][na], al, bh_[na]);
                }
            }
        }
    }

    // ---- epilogue: yl -> bf16 [n][c][j]; yr -> fp32 [c*NN+n][j] + bias ----
    const int quad = lane >> 2, qt = lane & 3;
    const bool isR = (col0 >= 256);
#pragma unroll
    for (int ma = 0; ma < 4; ma++) {
        int row0 = m0 + wm + ma * 16 + quad;
        int row1 = row0 + 8;
        if (!isR) {
            int c0 = row0 / NN, n0 = row0 - c0 * NN;
            int c1 = row1 / NN, n1 = row1 - c1 * NN;
            uint32_t* yb = (uint32_t*)g_ylb;
#pragma unroll
            for (int na = 0; na < 4; na++) {
                int cl = col0 + wn + na * 8 + qt * 2;   // 0..255
                __nv_bfloat162 p0 = __floats2bfloat162_rn(acc[ma][na][0], acc[ma][na][1]);
                __nv_bfloat162 p1 = __floats2bfloat162_rn(acc[ma][na][2], acc[ma][na][3]);
                yb[(((size_t)n0 * CC + c0) * FF + cl) >> 1] = *(uint32_t*)&p0;
                yb[(((size_t)n1 * CC + c1) * FF + cl) >> 1] = *(uint32_t*)&p1;
            }
        } else {
#pragma unroll
            for (int na = 0; na < 4; na++) {
                int jj = (col0 - 256) + wn + na * 8 + qt * 2;  // 0..255
                float b0 = bl[jj], b1 = bl[jj + 1];
                float2 v0; v0.x = acc[ma][na][0] + b0; v0.y = acc[ma][na][1] + b1;
                float2 v1; v1.x = acc[ma][na][2] + b0; v1.y = acc[ma][na][3] + b1;
                *(float2*)(g_yr + (size_t)row0 * FF + jj) = v0;
                *(float2*)(g_yr + (size_t)row1 * FF + jj) = v1;
            }
        }
    }
}

// ================= SAGE combine (CSR gather, bf16 yl in [n][c][j]) =================
// out x = relu(mean_agg(yl) + yr), written split bf16 to xh/xl
__global__ __launch_bounds__(256) void k_sage(int dstA) {
    __nv_bfloat16* __restrict__ oxh = dstA ? g_xhA : g_xhB;
    __nv_bfloat16* __restrict__ oxl = dstA ? g_xlA : g_xlB;
    int n = blockIdx.x;
    int t = threadIdx.x;
    int jp = t & 127;        // column pair j = 2*jp
    int ch = t >> 7;         // c half: c in [ch*8, ch*8+8)
    int e0 = g_rowptr[n], e1 = g_rowptr[n + 1];
    float inv = g_invdeg[n];

    float sacc[16];
#pragma unroll
    for (int q = 0; q < 16; q++) sacc[q] = 0.f;

    __shared__ int sc[256];
    for (int eb = e0; eb < e1; eb += 256) {
        int m = min(256, e1 - eb);
        __syncthreads();
        if (t < m) sc[t] = g_colidx[eb + t];
        __syncthreads();
        for (int q = 0; q < m; q++) {
            int src = sc[q];
            const uint32_t* p = (const uint32_t*)g_ylb
                                + (size_t)src * 2048 + ch * 1024 + jp;
#pragma unroll
            for (int cc = 0; cc < 8; cc++) {
                uint32_t u = p[cc * 128];
                __nv_bfloat162 b = *(__nv_bfloat162*)&u;
                float2 f = __bfloat1622float2(b);
                sacc[cc * 2]     += f.x;
                sacc[cc * 2 + 1] += f.y;
            }
        }
    }
#pragma unroll
    for (int cc = 0; cc < 8; cc++) {
        int c = ch * 8 + cc;
        size_t o = ((size_t)c * NN + n) * FF + jp * 2;
        float2 yr2 = *(const float2*)(g_yr + o);
        float2 v;
        v.x = fmaxf(sacc[cc * 2]     * inv + yr2.x, 0.f);
        v.y = fmaxf(sacc[cc * 2 + 1] * inv + yr2.y, 0.f);
        uint32_t hi, lo;
        split2(v, hi, lo);
        ((uint32_t*)oxh)[o >> 1] = hi;
        ((uint32_t*)oxl)[o >> 1] = lo;
    }
}

__global__ void k_pool() {
    int c = blockIdx.x, chunk = blockIdx.y, j = threadIdx.x;
    int n0 = chunk * 250;
    float acc = 0.f;
    for (int n = n0; n < n0 + 250; n++) {
        size_t o = ((size_t)c * NN + n) * FF + j;
        acc += __bfloat162float(g_xhA[o]) + __bfloat162float(g_xlA[o]);
    }
    atomicAdd(&g_pool[c * FF + j], acc);
}

__global__ __launch_bounds__(256) void k_mlp(
    const float* __restrict__ w1, const float* __restrict__ b1,
    const float* __restrict__ w2, const float* __restrict__ b2,
    const float* __restrict__ w3, const float* __restrict__ b3,
    float* __restrict__ outp)
{
    __shared__ float g[CC][FF];
    __shared__ float h[CC][FF];
    int j = threadIdx.x;
    const float scale = 1.0f / (float)NN;
#pragma unroll
    for (int c = 0; c < CC; c++) g[c][j] = g_pool[c * FF + j] * scale;
    __syncthreads();
    {
        float accs[CC];
#pragma unroll
        for (int c = 0; c < CC; c++) accs[c] = 0.f;
        for (int k = 0; k < FF; k++) {
            float wv = w1[k * FF + j];
#pragma unroll
            for (int c = 0; c < CC; c++) accs[c] += g[c][k] * wv;
        }
        float bb = b1[j];
#pragma unroll
        for (int c = 0; c < CC; c++) h[c][j] = fmaxf(accs[c] + bb, 0.f);
    }
    __syncthreads();
    {
        float accs[CC];
#pragma unroll
        for (int c = 0; c < CC; c++) accs[c] = 0.f;
        for (int k = 0; k < FF; k++) {
            float wv = w2[k * FF + j];
#pragma unroll
            for (int c = 0; c < CC; c++) accs[c] += h[c][k] * wv;
        }
        float bb = b2[j];
#pragma unroll
        for (int c = 0; c < CC; c++) g[c][j] = fmaxf(accs[c] + bb, 0.f);
    }
    __syncthreads();
    {
        float wv = w3[j];
#pragma unroll
        for (int c = 0; c < CC; c++) h[c][j] = g[c][j] * wv;
        __syncthreads();
        if (j < CC) {
            float s = 0.f;
            for (int k = 0; k < FF; k++) s += h[j][k];
            outp[j] = s + b3[0];
        }
    }
}

// ---------------------------------------------------------------------
extern "C" void kernel_launch(void* const* d_in, const int* in_sizes, int n_in,
                              void* d_out, int out_size) {
    const int*   x_node_cfg = (const int*)  d_in[0];
    const float* x_feat     = (const float*)d_in[1];
    const int*   x_op       = (const int*)  d_in[2];
    const int*   edge_index = (const int*)  d_in[3];
    const float* emb_op     = (const float*)d_in[4];
    const float* emb_layout = (const float*)d_in[5];
    const float* lin_w      = (const float*)d_in[6];
    const float* lin_b      = (const float*)d_in[7];
    const float* conv_wl    = (const float*)d_in[8];
    const float* conv_bl    = (const float*)d_in[9];
    const float* conv_wr    = (const float*)d_in[10];
    const float* w1         = (const float*)d_in[11];
    const float* b1         = (const float*)d_in[12];
    const float* w2         = (const float*)d_in[13];
    const float* b2         = (const float*)d_in[14];
    const float* w3         = (const float*)d_in[15];
    const float* b3         = (const float*)d_in[16];
    float* outp = (float*)d_out;

    cudaFuncSetAttribute(k_gemm_mma, cudaFuncAttributeMaxDynamicSharedMemorySize, 65536);

    // launch order: gemm layer 0 lands at profiled slot (index 3)
    k_wsplit<<<(4 * 512 * 256) / 256, 256>>>(conv_wl, conv_wr);            // 0
    k_tablebase<<<144 + NN, FF>>>(emb_layout, lin_w, lin_b,
                                  x_feat, x_op, emb_op);                    // 1
    k_initx<<<dim3(NN, CC), FF>>>(x_node_cfg);                              // 2
    k_gemm_mma<<<dim3(4, (CC * NN) / 128), 256, 65536>>>(1, 0, conv_bl);    // 3 (profiled)

    // CSR build (only needed by k_sage)
    k_small_zero<<<(NN + 255) / 256, 256>>>();                              // 4
    k_deg_acc<<<(EE + 255) / 256, 256>>>(edge_index);                       // 5
    k_scan<<<1, 256>>>();                                                   // 6
    k_fill<<<(EE + 255) / 256, 256>>>(edge_index);                          // 7
    k_sage<<<NN, 256>>>(0);                                                 // 8: layer0 -> B

    for (int i = 1; i < 4; i++) {
        int srcA = (i % 2 == 0) ? 1 : 0;
        k_gemm_mma<<<dim3(4, (CC * NN) / 128), 256, 65536>>>(
            srcA, i, conv_bl + (size_t)i * FF);
        k_sage<<<NN, 256>>>(srcA ? 0 : 1);
    }

    k_pool<<<dim3(CC, NN / 250), FF>>>();
    k_mlp<<<1, FF>>>(w1, b1, w2, b2, w3, b3, outp);
}

// round 11
// speedup vs baseline: 1.4142x; 1.1456x over previous
#include <cuda_runtime.h>
#include <cuda_bf16.h>
#include <cstdint>

#define CC 16
#define NN 10000
#define EE 40000
#define FF 256
#define CFGF 18

// ---- scratch (static __device__ arrays; no allocations anywhere) ----
// x kept as SPLIT bf16 (hi + residual lo), ping/pong
__device__ __nv_bfloat16 g_xhA[CC * NN * FF];
__device__ __nv_bfloat16 g_xlA[CC * NN * FF];
__device__ __nv_bfloat16 g_xhB[CC * NN * FF];
__device__ __nv_bfloat16 g_xlB[CC * NN * FF];
__device__ __nv_bfloat16 g_ylb[CC * NN * FF];   // x@wl, bf16, [node][c][j] (82MB, L2-resident)
__device__ float g_yr [CC * NN * FF];           // x@wr + bl, fp32, [c*NN+n][j]
__device__ float g_base[NN * FF];
__device__ float g_T   [CFGF * 8 * FF];
__device__ float g_invdeg[NN];
__device__ float g_pool[CC * FF];
__device__ int   g_deg[NN];
__device__ int   g_cursor[NN];
__device__ int   g_rowptr[NN + 1];
__device__ int   g_colidx[EE];
__device__ __nv_bfloat16 g_whi[4 * 512 * 256];  // weights split hi, [layer][n][k]
__device__ __nv_bfloat16 g_wlo[4 * 512 * 256];  // weights split lo

// ================= helpers =================
#define SWZ(o) ((o) ^ (((o) >> 3) & 0x70))

__device__ __forceinline__ uint32_t s2u(const void* p) {
    uint32_t a;
    asm("{ .reg .u64 t; cvta.to.shared.u64 t, %1; cvt.u32.u64 %0, t; }"
        : "=r"(a) : "l"(p));
    return a;
}
__device__ __forceinline__ void ldm_x4(uint32_t* r, uint32_t addr) {
    asm volatile("ldmatrix.sync.aligned.m8n8.x4.shared.b16 {%0,%1,%2,%3}, [%4];"
                 : "=r"(r[0]), "=r"(r[1]), "=r"(r[2]), "=r"(r[3]) : "r"(addr));
}
__device__ __forceinline__ void ldm_x2(uint32_t* r, uint32_t addr) {
    asm volatile("ldmatrix.sync.aligned.m8n8.x2.shared.b16 {%0,%1}, [%2];"
                 : "=r"(r[0]), "=r"(r[1]) : "r"(addr));
}
__device__ __forceinline__ void mma16816(float* d, const uint32_t* a, const uint32_t* b) {
    asm volatile(
        "mma.sync.aligned.m16n8k16.row.col.f32.bf16.bf16.f32 "
        "{%0,%1,%2,%3}, {%4,%5,%6,%7}, {%8,%9}, {%0,%1,%2,%3};"
        : "+f"(d[0]), "+f"(d[1]), "+f"(d[2]), "+f"(d[3])
        : "r"(a[0]), "r"(a[1]), "r"(a[2]), "r"(a[3]), "r"(b[0]), "r"(b[1]));
}
__device__ __forceinline__ void cp16(uint32_t saddr, const void* gptr) {
    asm volatile("cp.async.ca.shared.global [%0], [%1], 16;"
                 :: "r"(saddr), "l"(gptr) : "memory");
}
// split float2 -> packed bf16x2 hi and residual lo
__device__ __forceinline__ void split2(float2 v, uint32_t& hi, uint32_t& lo) {
    __nv_bfloat16 hx = __float2bfloat16(v.x), hy = __float2bfloat16(v.y);
    __nv_bfloat162 hp; hp.x = hx; hp.y = hy;
    __nv_bfloat162 lp = __floats2bfloat162_rn(v.x - __bfloat162float(hx),
                                              v.y - __bfloat162float(hy));
    hi = *(uint32_t*)&hp; lo = *(uint32_t*)&lp;
}

// ================= prologue kernels =================
__global__ void k_tablebase(const float* __restrict__ emb_layout,
                            const float* __restrict__ lin_w,
                            const float* __restrict__ lin_b,
                            const float* __restrict__ x_feat,
                            const int*   __restrict__ x_op,
                            const float* __restrict__ emb_op) {
    int j = threadIdx.x;
    if (blockIdx.x < 144) {
        int blk = blockIdx.x;
        int k = blk >> 3, v = blk & 7;
        float acc = 0.f;
#pragma unroll
        for (int d = 0; d < 4; d++)
            acc += emb_layout[v * 4 + d] * lin_w[(140 + k * 4 + d) * FF + j];
        g_T[blk * FF + j] = acc;
        return;
    }
    int n = blockIdx.x - 144;
    __shared__ float sf[144];
    if (j < 140) sf[j] = x_feat[n * 140 + j];
    if (j >= 140 && j < 144) {
        int op = x_op[n];
        sf[j] = emb_op[op * 4 + (j - 140)];
    }
    __syncthreads();
    float acc = lin_b[j];
#pragma unroll 4
    for (int d = 0; d < 140; d++) acc += sf[d] * lin_w[d * FF + j];
#pragma unroll
    for (int d = 0; d < 4; d++)   acc += sf[140 + d] * lin_w[(212 + d) * FF + j];
    g_base[n * FF + j] = acc;
}

__global__ void k_small_zero() {
    int i = blockIdx.x * blockDim.x + threadIdx.x;
    if (i < NN) { g_deg[i] = 0; g_cursor[i] = 0; }
    if (i < CC * FF) g_pool[i] = 0.f;
}
__global__ void k_deg_acc(const int* __restrict__ edge_index) {
    int e = blockIdx.x * blockDim.x + threadIdx.x;
    if (e < EE) atomicAdd(&g_deg[edge_index[EE + e]], 1);
}
__global__ void k_scan() {
    __shared__ int csum[256];
    int t = threadIdx.x;
    const int CH = (NN + 255) / 256;  // 40
    int base = t * CH;
    int s = 0;
    for (int i = 0; i < CH; i++) {
        int idx = base + i;
        if (idx < NN) s += g_deg[idx];
    }
    csum[t] = s;
    __syncthreads();
    if (t == 0) {
        int acc = 0;
        for (int i = 0; i < 256; i++) { int v = csum[i]; csum[i] = acc; acc += v; }
        g_rowptr[NN] = acc;
    }
    __syncthreads();
    int acc = csum[t];
    for (int i = 0; i < CH; i++) {
        int idx = base + i;
        if (idx < NN) {
            g_rowptr[idx] = acc;
            int d = g_deg[idx];
            acc += d;
            g_invdeg[idx] = 1.0f / fmaxf((float)d, 1.0f);
        }
    }
}
__global__ void k_fill(const int* __restrict__ edge_index) {
    int e = blockIdx.x * blockDim.x + threadIdx.x;
    if (e < EE) {
        int dst = edge_index[EE + e];
        int p = atomicAdd(&g_cursor[dst], 1);
        g_colidx[g_rowptr[dst] + p] = edge_index[e];
    }
}

// x0 = base + sum_k T[k][cfg] -> split bf16 into xhA/xlA
__global__ void k_initx(const int* __restrict__ x_node_cfg) {
    int n = blockIdx.x, c = blockIdx.y, j = threadIdx.x;
    __shared__ int scfg[CFGF];
    if (j < CFGF) scfg[j] = x_node_cfg[((size_t)c * NN + n) * CFGF + j];
    __syncthreads();
    float acc = g_base[n * FF + j];
#pragma unroll
    for (int k = 0; k < CFGF; k++)
        acc += g_T[(k * 8 + scfg[k]) * FF + j];
    size_t o = ((size_t)c * NN + n) * FF + j;
    __nv_bfloat16 h = __float2bfloat16(acc);
    g_xhA[o] = h;
    g_xlA[o] = __float2bfloat16(acc - __bfloat162float(h));
}

// split all 4 layers' weights into bf16 hi/lo in [layer][n(512)][k(256)] layout
__global__ void k_wsplit(const float* __restrict__ conv_wl,
                         const float* __restrict__ conv_wr) {
    int t = blockIdx.x * 256 + threadIdx.x;
    int l = t >> 17;
    int rem = t & 131071;
    int n = rem >> 8, k = rem & 255;
    const float* w = (n < 256) ? (conv_wl + (size_t)l * 65536)
                               : (conv_wr + (size_t)l * 65536);
    float v = w[k * 256 + (n & 255)];
    __nv_bfloat16 h = __float2bfloat16(v);
    g_whi[t] = h;
    g_wlo[t] = __float2bfloat16(v - __bfloat162float(h));
}

// ================= HMMA bf16x3 GEMM =================
// y = x @ [wl | wr]  (M=160000, K=256, N=512)
// CTA 128x128, 256 threads, 8 warps (2m x 4n), warp tile 64x32.
// x pre-split bf16 -> all 4 tiles via cp.async; no conversion.
// smem 64KB single stage; __launch_bounds__(256,2) forces <=128 regs so
// 2 CTAs/SM co-reside: one CTA's MMA phase hides the other's load phase.
__global__ __launch_bounds__(256, 2) void k_gemm_mma(int srcA, int layer,
                                                     const float* __restrict__ bl) {
    extern __shared__ __align__(128) char smem[];
    const __nv_bfloat16* __restrict__ xh = srcA ? g_xhA : g_xhB;
    const __nv_bfloat16* __restrict__ xl = srcA ? g_xlA : g_xlB;

    const int tid = threadIdx.x;
    const int wid = tid >> 5, lane = tid & 31;
    const int col0 = blockIdx.x * 128;
    const int m0 = blockIdx.y * 128;
    const int wm = (wid & 1) * 64;       // warp m base
    const int wn = (wid >> 1) * 32;      // warp n base

    const uint32_t sbase = s2u(smem);
    const uint32_t sA_hi = sbase;
    const uint32_t sA_lo = sbase + 16384;
    const uint32_t sB_hi = sbase + 32768;
    const uint32_t sB_lo = sbase + 49152;

    float acc[4][4][4];
#pragma unroll
    for (int i = 0; i < 4; i++)
#pragma unroll
        for (int j = 0; j < 4; j++)
#pragma unroll
            for (int q = 0; q < 4; q++) acc[i][j][q] = 0.f;

    const int r = tid >> 1, half = tid & 1;   // r: 0..127, half: 0/1 (32-elem halves)
    const __nv_bfloat16* ahp = xh + (size_t)(m0 + r) * FF + half * 32;
    const __nv_bfloat16* alp = xl + (size_t)(m0 + r) * FF + half * 32;
    const __nv_bfloat16* bhp = g_whi + (size_t)(layer * 512 + col0 + r) * 256 + half * 32;
    const __nv_bfloat16* blp = g_wlo + (size_t)(layer * 512 + col0 + r) * 256 + half * 32;

    for (int kc = 0; kc < 4; kc++) {
        __syncthreads();   // prev compute done reading smem
#pragma unroll
        for (int q = 0; q < 4; q++) {
            uint32_t so = SWZ((uint32_t)(r * 128 + half * 64 + q * 16));
            cp16(sA_hi + so, ahp + kc * 64 + q * 8);
            cp16(sA_lo + so, alp + kc * 64 + q * 8);
            cp16(sB_hi + so, bhp + kc * 64 + q * 8);
            cp16(sB_lo + so, blp + kc * 64 + q * 8);
        }
        asm volatile("cp.async.commit_group;" ::: "memory");
        asm volatile("cp.async.wait_group 0;" ::: "memory");
        __syncthreads();

#pragma unroll
        for (int ks = 0; ks < 4; ks++) {
            uint32_t bh_[4][2], bl_[4][2];
#pragma unroll
            for (int na = 0; na < 4; na++) {
                uint32_t o = (uint32_t)((wn + na * 8 + (lane & 7)) * 128);
                uint32_t seg = (uint32_t)((ks * 2 + ((lane >> 3) & 1)) * 16);
                uint32_t ad = o + (seg ^ ((o >> 3) & 0x70));
                ldm_x2(bh_[na], sB_hi + ad);
                ldm_x2(bl_[na], sB_lo + ad);
            }
#pragma unroll
            for (int ma = 0; ma < 4; ma++) {
                uint32_t o = (uint32_t)((wm + ma * 16 + (lane & 15)) * 128);
                uint32_t seg = (uint32_t)((ks * 2 + (lane >> 4)) * 16);
                uint32_t ad = o + (seg ^ ((o >> 3) & 0x70));
                uint32_t ah[4], al[4];
                ldm_x4(ah, sA_hi + ad);
                ldm_x4(al, sA_lo + ad);
#pragma unroll
                for (int na = 0; na < 4; na++) {
                    mma16816(acc[ma][na], ah, bh_[na]);
                    mma16816(acc[ma][na], ah, bl_[na]);
                    mma16816(acc[ma][na], al, bh_[na]);
                }
            }
        }
    }

    // ---- epilogue: yl -> bf16 [n][c][j]; yr -> fp32 [c*NN+n][j] + bias ----
    const int quad = lane >> 2, qt = lane & 3;
    const bool isR = (col0 >= 256);
#pragma unroll
    for (int ma = 0; ma < 4; ma++) {
        int row0 = m0 + wm + ma * 16 + quad;
        int row1 = row0 + 8;
        if (!isR) {
            int c0 = row0 / NN, n0 = row0 - c0 * NN;
            int c1 = row1 / NN, n1 = row1 - c1 * NN;
            uint32_t* yb = (uint32_t*)g_ylb;
#pragma unroll
            for (int na = 0; na < 4; na++) {
                int cl = col0 + wn + na * 8 + qt * 2;   // 0..255
                __nv_bfloat162 p0 = __floats2bfloat162_rn(acc[ma][na][0], acc[ma][na][1]);
                __nv_bfloat162 p1 = __floats2bfloat162_rn(acc[ma][na][2], acc[ma][na][3]);
                yb[(((size_t)n0 * CC + c0) * FF + cl) >> 1] = *(uint32_t*)&p0;
                yb[(((size_t)n1 * CC + c1) * FF + cl) >> 1] = *(uint32_t*)&p1;
            }
        } else {
#pragma unroll
            for (int na = 0; na < 4; na++) {
                int jj = (col0 - 256) + wn + na * 8 + qt * 2;  // 0..255
                float b0 = bl[jj], b1 = bl[jj + 1];
                float2 v0; v0.x = acc[ma][na][0] + b0; v0.y = acc[ma][na][1] + b1;
                float2 v1; v1.x = acc[ma][na][2] + b0; v1.y = acc[ma][na][3] + b1;
                *(float2*)(g_yr + (size_t)row0 * FF + jj) = v0;
                *(float2*)(g_yr + (size_t)row1 * FF + jj) = v1;
            }
        }
    }
}

// ================= SAGE combine (CSR gather, bf16 yl in [n][c][j]) =================
// out x = relu(mean_agg(yl) + yr), written split bf16 to xh/xl
__global__ __launch_bounds__(256) void k_sage(int dstA) {
    __nv_bfloat16* __restrict__ oxh = dstA ? g_xhA : g_xhB;
    __nv_bfloat16* __restrict__ oxl = dstA ? g_xlA : g_xlB;
    int n = blockIdx.x;
    int t = threadIdx.x;
    int jp = t & 127;        // column pair j = 2*jp
    int ch = t >> 7;         // c half: c in [ch*8, ch*8+8)
    int e0 = g_rowptr[n], e1 = g_rowptr[n + 1];
    float inv = g_invdeg[n];

    float sacc[16];
#pragma unroll
    for (int q = 0; q < 16; q++) sacc[q] = 0.f;

    __shared__ int sc[256];
    for (int eb = e0; eb < e1; eb += 256) {
        int m = min(256, e1 - eb);
        __syncthreads();
        if (t < m) sc[t] = g_colidx[eb + t];
        __syncthreads();
        for (int q = 0; q < m; q++) {
            int src = sc[q];
            const uint32_t* p = (const uint32_t*)g_ylb
                                + (size_t)src * 2048 + ch * 1024 + jp;
#pragma unroll
            for (int cc = 0; cc < 8; cc++) {
                uint32_t u = p[cc * 128];
                __nv_bfloat162 b = *(__nv_bfloat162*)&u;
                float2 f = __bfloat1622float2(b);
                sacc[cc * 2]     += f.x;
                sacc[cc * 2 + 1] += f.y;
            }
        }
    }
#pragma unroll
    for (int cc = 0; cc < 8; cc++) {
        int c = ch * 8 + cc;
        size_t o = ((size_t)c * NN + n) * FF + jp * 2;
        float2 yr2 = *(const float2*)(g_yr + o);
        float2 v;
        v.x = fmaxf(sacc[cc * 2]     * inv + yr2.x, 0.f);
        v.y = fmaxf(sacc[cc * 2 + 1] * inv + yr2.y, 0.f);
        uint32_t hi, lo;
        split2(v, hi, lo);
        ((uint32_t*)oxh)[o >> 1] = hi;
        ((uint32_t*)oxl)[o >> 1] = lo;
    }
}

__global__ void k_pool() {
    int c = blockIdx.x, chunk = blockIdx.y, j = threadIdx.x;
    int n0 = chunk * 250;
    float acc = 0.f;
    for (int n = n0; n < n0 + 250; n++) {
        size_t o = ((size_t)c * NN + n) * FF + j;
        acc += __bfloat162float(g_xhA[o]) + __bfloat162float(g_xlA[o]);
    }
    atomicAdd(&g_pool[c * FF + j], acc);
}

__global__ __launch_bounds__(256) void k_mlp(
    const float* __restrict__ w1, const float* __restrict__ b1,
    const float* __restrict__ w2, const float* __restrict__ b2,
    const float* __restrict__ w3, const float* __restrict__ b3,
    float* __restrict__ outp)
{
    __shared__ float g[CC][FF];
    __shared__ float h[CC][FF];
    int j = threadIdx.x;
    const float scale = 1.0f / (float)NN;
#pragma unroll
    for (int c = 0; c < CC; c++) g[c][j] = g_pool[c * FF + j] * scale;
    __syncthreads();
    {
        float accs[CC];
#pragma unroll
        for (int c = 0; c < CC; c++) accs[c] = 0.f;
        for (int k = 0; k < FF; k++) {
            float wv = w1[k * FF + j];
#pragma unroll
            for (int c = 0; c < CC; c++) accs[c] += g[c][k] * wv;
        }
        float bb = b1[j];
#pragma unroll
        for (int c = 0; c < CC; c++) h[c][j] = fmaxf(accs[c] + bb, 0.f);
    }
    __syncthreads();
    {
        float accs[CC];
#pragma unroll
        for (int c = 0; c < CC; c++) accs[c] = 0.f;
        for (int k = 0; k < FF; k++) {
            float wv = w2[k * FF + j];
#pragma unroll
            for (int c = 0; c < CC; c++) accs[c] += h[c][k] * wv;
        }
        float bb = b2[j];
#pragma unroll
        for (int c = 0; c < CC; c++) g[c][j] = fmaxf(accs[c] + bb, 0.f);
    }
    __syncthreads();
    {
        float wv = w3[j];
#pragma unroll
        for (int c = 0; c < CC; c++) h[c][j] = g[c][j] * wv;
        __syncthreads();
        if (j < CC) {
            float s = 0.f;
            for (int k = 0; k < FF; k++) s += h[j][k];
            outp[j] = s + b3[0];
        }
    }
}

// ---------------------------------------------------------------------
extern "C" void kernel_launch(void* const* d_in, const int* in_sizes, int n_in,
                              void* d_out, int out_size) {
    const int*   x_node_cfg = (const int*)  d_in[0];
    const float* x_feat     = (const float*)d_in[1];
    const int*   x_op       = (const int*)  d_in[2];
    const int*   edge_index = (const int*)  d_in[3];
    const float* emb_op     = (const float*)d_in[4];
    const float* emb_layout = (const float*)d_in[5];
    const float* lin_w      = (const float*)d_in[6];
    const float* lin_b      = (const float*)d_in[7];
    const float* conv_wl    = (const float*)d_in[8];
    const float* conv_bl    = (const float*)d_in[9];
    const float* conv_wr    = (const float*)d_in[10];
    const float* w1         = (const float*)d_in[11];
    const float* b1         = (const float*)d_in[12];
    const float* w2         = (const float*)d_in[13];
    const float* b2         = (const float*)d_in[14];
    const float* w3         = (const float*)d_in[15];
    const float* b3         = (const float*)d_in[16];
    float* outp = (float*)d_out;

    cudaFuncSetAttribute(k_gemm_mma, cudaFuncAttributeMaxDynamicSharedMemorySize, 65536);

    // launch order: gemm layer 0 lands at profiled slot (index 3)
    k_wsplit<<<(4 * 512 * 256) / 256, 256>>>(conv_wl, conv_wr);            // 0
    k_tablebase<<<144 + NN, FF>>>(emb_layout, lin_w, lin_b,
                                  x_feat, x_op, emb_op);                    // 1
    k_initx<<<dim3(NN, CC), FF>>>(x_node_cfg);                              // 2
    k_gemm_mma<<<dim3(4, (CC * NN) / 128), 256, 65536>>>(1, 0, conv_bl);    // 3 (profiled)

    // CSR build (only needed by k_sage)
    k_small_zero<<<(NN + 255) / 256, 256>>>();                              // 4
    k_deg_acc<<<(EE + 255) / 256, 256>>>(edge_index);                       // 5
    k_scan<<<1, 256>>>();                                                   // 6
    k_fill<<<(EE + 255) / 256, 256>>>(edge_index);                          // 7
    k_sage<<<NN, 256>>>(0);                                                 // 8: layer0 -> B

    for (int i = 1; i < 4; i++) {
        int srcA = (i % 2 == 0) ? 1 : 0;
        k_gemm_mma<<<dim3(4, (CC * NN) / 128), 256, 65536>>>(
            srcA, i, conv_bl + (size_t)i * FF);
        k_sage<<<NN, 256>>>(srcA ? 0 : 1);
    }

    k_pool<<<dim3(CC, NN / 250), FF>>>();
    k_mlp<<<1, FF>>>(w1, b1, w2, b2, w3, b3, outp);
}